// round 3
// baseline (speedup 1.0000x reference)
#include <cuda_runtime.h>
#include <cstdint>

// Problem constants (fixed by the dataset; runtime values are read from
// in_sizes and used for loop bounds, these size the static scratch).
#define MAXN 50000

// ---------------- device scratch (no allocations allowed) ----------------
__device__ __align__(16) float    g_h1  [MAXN * 128];  // layer1 features  [N,H=8,C=16]
__device__ __align__(16) float    g_h1e [MAXN * 128];  // after softmax-agg + elu
__device__ __align__(16) float    g_out1[MAXN * 128];  // layer1 numerator accum
__device__ __align__(16) float    g_sA1 [MAXN * 8];    // dot(h1, att_src1) -> used at dst
__device__ __align__(16) float    g_sB1 [MAXN * 8];    // dot(h1, att_dst1) -> used at src
__device__ __align__(16) unsigned g_amax1[MAXN * 8];   // encoded segment max
__device__ __align__(16) float    g_den1[MAXN * 8];    // softmax denominator
__device__ __align__(16) float    g_h2  [MAXN * 16];   // layer2 features [N,16]
__device__ __align__(16) float    g_out2[MAXN * 16];   // layer2 numerator accum
__device__ float    g_sA2 [MAXN];
__device__ float    g_sB2 [MAXN];
__device__ unsigned g_amax2[MAXN];
__device__ float    g_den2[MAXN];

// ------------- order-preserving float <-> uint for atomicMax --------------
__device__ __forceinline__ unsigned f2o(float f) {
    unsigned u = __float_as_uint(f);
    return (u & 0x80000000u) ? ~u : (u | 0x80000000u);
}
__device__ __forceinline__ float o2f(unsigned e) {
    return __uint_as_float((e & 0x80000000u) ? (e ^ 0x80000000u) : ~e);
}

// vectorized float4 reduction to global (sm_90+): 1 instr instead of 4 atomics
__device__ __forceinline__ void red_add_v4(float4* p, float a, float b, float c, float d) {
    asm volatile("red.global.add.v4.f32 [%0], {%1,%2,%3,%4};"
                 :: "l"(p), "f"(a), "f"(b), "f"(c), "f"(d) : "memory");
}

__device__ __forceinline__ float lrelu(float x) { return x > 0.f ? x : 0.2f * x; }

// --------------------------- zero scratch ---------------------------------
__global__ void k_zero(int n) {
    int i = blockIdx.x * blockDim.x + threadIdx.x;
    float4 z = make_float4(0.f, 0.f, 0.f, 0.f);
    if (i < n * 32) ((float4*)g_out1)[i] = z;            // n*128 floats
    if (i < n * 4)  ((float4*)g_out2)[i] = z;            // n*16 floats
    if (i < n * 2) {                                     // n*8 entries
        ((float4*)g_den1)[i] = z;
        ((uint4*)g_amax1)[i] = make_uint4(0u, 0u, 0u, 0u);
    }
    if (i < n) { g_den2[i] = 0.f; g_amax2[i] = 0u; }
}

// ------------------- GEMM1: h1 = x @ W1^T  (N,128)x(128,128) --------------
// block = 128 threads (one per output channel), 16 nodes per block.
// x tile lives in smem (broadcast reads), W1 rows read via L1 (64KB resident).
__global__ void k_gemm1(const float* __restrict__ x, const float* __restrict__ W, int n) {
    __shared__ float4 xs[16][32];
    int o  = threadIdx.x;           // output channel 0..127
    int n0 = blockIdx.x * 16;
    const float4* xv = (const float4*)x;
#pragma unroll
    for (int r = 0; r < 4; r++) {
        int idx = r * 128 + o;      // 512 float4 in tile
        int i = idx >> 5, k4 = idx & 31;
        int node = n0 + i;
        xs[i][k4] = (node < n) ? xv[node * 32 + k4] : make_float4(0.f,0.f,0.f,0.f);
    }
    __syncthreads();
    const float4* Wv = (const float4*)W;
    float acc[16];
#pragma unroll
    for (int i = 0; i < 16; i++) acc[i] = 0.f;
#pragma unroll 4
    for (int k4 = 0; k4 < 32; k4++) {
        float4 w = __ldg(&Wv[o * 32 + k4]);
#pragma unroll
        for (int i = 0; i < 16; i++) {
            float4 xq = xs[i][k4];
            acc[i] = fmaf(w.x, xq.x, fmaf(w.y, xq.y, fmaf(w.z, xq.z, fmaf(w.w, xq.w, acc[i]))));
        }
    }
#pragma unroll
    for (int i = 0; i < 16; i++) {
        int node = n0 + i;
        if (node < n) g_h1[node * 128 + o] = acc[i];
    }
}

// --------- per-node attention scalars, layer 1 (thread per (n,h)) ---------
__global__ void k_att1(const float* __restrict__ att_src, const float* __restrict__ att_dst, int n) {
    int t = blockIdx.x * blockDim.x + threadIdx.x;
    if (t >= n * 8) return;
    int nd = t >> 3, h = t & 7;
    const float4* hv = (const float4*)g_h1 + nd * 32 + h * 4;
    const float4* as = (const float4*)att_src + h * 4;
    const float4* ad = (const float4*)att_dst + h * 4;
    float sa = 0.f, sb = 0.f;
#pragma unroll
    for (int j = 0; j < 4; j++) {
        float4 hq = hv[j], aq = as[j], dq = ad[j];
        sa += hq.x*aq.x + hq.y*aq.y + hq.z*aq.z + hq.w*aq.w;
        sb += hq.x*dq.x + hq.y*dq.y + hq.z*dq.z + hq.w*dq.w;
    }
    g_sA1[t] = sa;  // pairs with dst
    g_sB1[t] = sb;  // pairs with src
}

// -------------------- edge pass A layer1: segment max ---------------------
__global__ void k_emax1(const int* __restrict__ ei, int e, int n) {
    int t = blockIdx.x * blockDim.x + threadIdx.x;
    int ep = e + n;
    if (t >= ep) return;
    int s, d;
    if (t < e) { s = ei[t]; d = ei[e + t]; } else { s = d = t - e; }
    const float4* A = (const float4*)g_sA1 + d * 2;
    const float4* B = (const float4*)g_sB1 + s * 2;
    float4 a0 = A[0], a1 = A[1], b0 = B[0], b1 = B[1];
    float v[8] = { a0.x+b0.x, a0.y+b0.y, a0.z+b0.z, a0.w+b0.w,
                   a1.x+b1.x, a1.y+b1.y, a1.z+b1.z, a1.w+b1.w };
#pragma unroll
    for (int h = 0; h < 8; h++)
        atomicMax(&g_amax1[d * 8 + h], f2o(lrelu(v[h])));
}

// -------- edge pass B layer1: exp + denom + numerator scatter -------------
// thread per (edge, head): 1 scalar atomicAdd + 4 red.v4 (16 channels)
__global__ void k_esc1(const int* __restrict__ ei, int e, int n) {
    int t = blockIdx.x * blockDim.x + threadIdx.x;
    int ep = e + n;
    if (t >= ep * 8) return;
    int ed = t >> 3, h = t & 7;
    int s, d;
    if (ed < e) { s = ei[ed]; d = ei[e + ed]; } else { s = d = ed - e; }
    float a = lrelu(g_sA1[d * 8 + h] + g_sB1[s * 8 + h]);
    float m = o2f(g_amax1[d * 8 + h]);
    float ex = __expf(a - m);
    atomicAdd(&g_den1[d * 8 + h], ex);
    const float4* hv = (const float4*)g_h1 + s * 32 + h * 4;
    float4* ov = (float4*)g_out1 + d * 32 + h * 4;
#pragma unroll
    for (int j = 0; j < 4; j++) {
        float4 hq = hv[j];
        red_add_v4(ov + j, ex*hq.x, ex*hq.y, ex*hq.z, ex*hq.w);
    }
}

// --------------- finalize layer1: divide, +bias, ELU ----------------------
__global__ void k_fin1(const float* __restrict__ b1, int n) {
    int t = blockIdx.x * blockDim.x + threadIdx.x;
    if (t >= n * 128) return;
    int nd = t >> 7, c = t & 127;
    float v = g_out1[t] / g_den1[nd * 8 + (c >> 4)] + b1[c];
    g_h1e[t] = v > 0.f ? v : (__expf(v) - 1.f);   // ELU(alpha=1)
}

// ------------------- GEMM2: h2 = h1e @ W2^T  (N,128)x(128,16) -------------
__global__ void k_gemm2(const float* __restrict__ W2, int n) {
    __shared__ float4 xs[8][32];
    int tid = threadIdx.x;          // 128 threads
    int n0 = blockIdx.x * 8;
    const float4* hv = (const float4*)g_h1e;
#pragma unroll
    for (int r = 0; r < 2; r++) {
        int idx = r * 128 + tid;    // 256 float4 in tile
        int i = idx >> 5, k4 = idx & 31;
        int node = n0 + i;
        xs[i][k4] = (node < n) ? hv[node * 32 + k4] : make_float4(0.f,0.f,0.f,0.f);
    }
    __syncthreads();
    int o = tid & 15, i = tid >> 4;
    const float4* Wv = (const float4*)W2;
    float acc = 0.f;
#pragma unroll 4
    for (int k4 = 0; k4 < 32; k4++) {
        float4 w = __ldg(&Wv[o * 32 + k4]);
        float4 xq = xs[i][k4];
        acc = fmaf(w.x, xq.x, fmaf(w.y, xq.y, fmaf(w.z, xq.z, fmaf(w.w, xq.w, acc))));
    }
    int node = n0 + i;
    if (node < n) g_h2[node * 16 + o] = acc;
}

// ------------- per-node attention scalars, layer 2 ------------------------
__global__ void k_att2(const float* __restrict__ att_src, const float* __restrict__ att_dst, int n) {
    int t = blockIdx.x * blockDim.x + threadIdx.x;
    if (t >= n) return;
    const float4* hv = (const float4*)g_h2 + t * 4;
    const float4* as = (const float4*)att_src;
    const float4* ad = (const float4*)att_dst;
    float sa = 0.f, sb = 0.f;
#pragma unroll
    for (int j = 0; j < 4; j++) {
        float4 hq = hv[j], aq = as[j], dq = ad[j];
        sa += hq.x*aq.x + hq.y*aq.y + hq.z*aq.z + hq.w*aq.w;
        sb += hq.x*dq.x + hq.y*dq.y + hq.z*dq.z + hq.w*dq.w;
    }
    g_sA2[t] = sa;
    g_sB2[t] = sb;
}

// ---------------------- edge passes layer 2 -------------------------------
__global__ void k_emax2(const int* __restrict__ ei, int e, int n) {
    int t = blockIdx.x * blockDim.x + threadIdx.x;
    int ep = e + n;
    if (t >= ep) return;
    int s, d;
    if (t < e) { s = ei[t]; d = ei[e + t]; } else { s = d = t - e; }
    atomicMax(&g_amax2[d], f2o(lrelu(g_sA2[d] + g_sB2[s])));
}

__global__ void k_esc2(const int* __restrict__ ei, int e, int n) {
    int t = blockIdx.x * blockDim.x + threadIdx.x;
    int ep = e + n;
    if (t >= ep) return;
    int s, d;
    if (t < e) { s = ei[t]; d = ei[e + t]; } else { s = d = t - e; }
    float a = lrelu(g_sA2[d] + g_sB2[s]);
    float ex = __expf(a - o2f(g_amax2[d]));
    atomicAdd(&g_den2[d], ex);
    const float4* hv = (const float4*)g_h2 + s * 4;
    float4* ov = (float4*)g_out2 + d * 4;
#pragma unroll
    for (int j = 0; j < 4; j++) {
        float4 hq = hv[j];
        red_add_v4(ov + j, ex*hq.x, ex*hq.y, ex*hq.z, ex*hq.w);
    }
}

// ------------- finalize layer2: divide, +bias, log_softmax ----------------
__global__ void k_fin2(const float* __restrict__ b2, float* __restrict__ out, int n) {
    int t = blockIdx.x * blockDim.x + threadIdx.x;
    if (t >= n) return;
    float inv = 1.f / g_den2[t];
    float v[16];
    const float4* ov = (const float4*)g_out2 + t * 4;
    const float4* bv = (const float4*)b2;
#pragma unroll
    for (int j = 0; j < 4; j++) {
        float4 q = ov[j], b = bv[j];
        v[j*4+0] = q.x * inv + b.x;
        v[j*4+1] = q.y * inv + b.y;
        v[j*4+2] = q.z * inv + b.z;
        v[j*4+3] = q.w * inv + b.w;
    }
    float m = v[0];
#pragma unroll
    for (int j = 1; j < 16; j++) m = fmaxf(m, v[j]);
    float sum = 0.f;
#pragma unroll
    for (int j = 0; j < 16; j++) sum += __expf(v[j] - m);
    float l = m + logf(sum);
    float4* od = (float4*)out + t * 4;
#pragma unroll
    for (int j = 0; j < 4; j++)
        od[j] = make_float4(v[j*4+0]-l, v[j*4+1]-l, v[j*4+2]-l, v[j*4+3]-l);
}

// ---------------------------------------------------------------------------
extern "C" void kernel_launch(void* const* d_in, const int* in_sizes, int n_in,
                              void* d_out, int out_size) {
    const float* x   = (const float*)d_in[0];
    const int*   ei  = (const int*)  d_in[1];
    const float* W1  = (const float*)d_in[2];
    const float* as1 = (const float*)d_in[3];
    const float* ad1 = (const float*)d_in[4];
    const float* b1  = (const float*)d_in[5];
    const float* W2  = (const float*)d_in[6];
    const float* as2 = (const float*)d_in[7];
    const float* ad2 = (const float*)d_in[8];
    const float* b2  = (const float*)d_in[9];
    float* out = (float*)d_out;

    int n  = in_sizes[0] / 128;   // 50000 nodes
    int e  = in_sizes[1] / 2;     // 1.6M edges (before self loops)
    int ep = e + n;

    const int BS = 256;
    k_zero <<<(n * 32 + BS - 1) / BS, BS>>>(n);
    k_gemm1<<<(n + 15) / 16, 128>>>(x, W1, n);
    k_att1 <<<(n * 8 + BS - 1) / BS, BS>>>(as1, ad1, n);
    k_emax1<<<(ep + BS - 1) / BS, BS>>>(ei, e, n);
    k_esc1 <<<(ep * 8 + BS - 1) / BS, BS>>>(ei, e, n);
    k_fin1 <<<(n * 128 + BS - 1) / BS, BS>>>(b1, n);
    k_gemm2<<<(n + 7) / 8, 128>>>(W2, n);
    k_att2 <<<(n + BS - 1) / BS, BS>>>(as2, ad2, n);
    k_emax2<<<(ep + BS - 1) / BS, BS>>>(ei, e, n);
    k_esc2 <<<(ep + BS - 1) / BS, BS>>>(ei, e, n);
    k_fin2 <<<(n + BS - 1) / BS, BS>>>(b2, out, n);
}

// round 4
// speedup vs baseline: 1.6038x; 1.6038x over previous
#include <cuda_runtime.h>
#include <cstdint>

#define MAXN 50000
#define MAXE 1600000

// ---------------- device scratch (no allocations allowed) ----------------
__device__ __align__(16) float g_h1 [MAXN * 128];  // layer1 features  [N,H=8,C=16]
__device__ __align__(16) float g_h1e[MAXN * 128];  // layer1 output after agg+bias+ELU
__device__ __align__(16) float g_sA1[MAXN * 8];    // dot(h1, att_src1) -> used at dst
__device__ __align__(16) float g_sB1[MAXN * 8];    // dot(h1, att_dst1) -> used at src
__device__ __align__(16) float g_h2 [MAXN * 16];   // layer2 features [N,16]
__device__ float g_sA2[MAXN];
__device__ float g_sB2[MAXN];
// CSR by destination (self loops included)
__device__ int g_deg[MAXN];
__device__ int g_rp [MAXN + 1];
__device__ int g_cur[MAXN];
__device__ int g_csr[MAXE + MAXN];

__device__ __forceinline__ float lrelu(float x) { return x > 0.f ? x : 0.2f * x; }

// ------------------------- CSR build --------------------------------------
__global__ void k_deginit(int n) {
    int i = blockIdx.x * blockDim.x + threadIdx.x;
    if (i < n) g_deg[i] = 1;                 // self loop pre-counted
}

__global__ void k_hist(const int* __restrict__ ei, int e) {
    int t = blockIdx.x * blockDim.x + threadIdx.x;
    if (t < e) atomicAdd(&g_deg[ei[e + t]], 1);
}

// single-block exclusive scan of g_deg -> g_rp (and g_cur copy)
__global__ void k_scan(int n) {
    __shared__ int ssum[1024];
    int tid = threadIdx.x;
    int chunk = (n + 1023) >> 10;
    int start = tid * chunk;
    int stop  = min(start + chunk, n);
    int sum = 0;
    for (int i = start; i < stop; i++) sum += g_deg[i];
    ssum[tid] = sum;
    __syncthreads();
    for (int off = 1; off < 1024; off <<= 1) {
        int t = (tid >= off) ? ssum[tid - off] : 0;
        __syncthreads();
        ssum[tid] += t;
        __syncthreads();
    }
    int run = ssum[tid] - sum;               // exclusive prefix
    for (int i = start; i < stop; i++) {
        int d = g_deg[i];
        g_rp[i]  = run;
        g_cur[i] = run;
        run += d;
    }
    if (tid == 1023) g_rp[n] = ssum[1023];
}

__global__ void k_scatter(const int* __restrict__ ei, int e, int n) {
    int t = blockIdx.x * blockDim.x + threadIdx.x;
    int ep = e + n;
    if (t >= ep) return;
    int s, d;
    if (t < e) { s = ei[t]; d = ei[e + t]; } else { s = d = t - e; }
    int pos = atomicAdd(&g_cur[d], 1);
    g_csr[pos] = s;
}

// ------------------- GEMM1: h1 = x @ W1^T  (N,128)x(128,128) --------------
__global__ void k_gemm1(const float* __restrict__ x, const float* __restrict__ W, int n) {
    __shared__ float4 xs[16][32];
    int o  = threadIdx.x;                    // output channel 0..127
    int n0 = blockIdx.x * 16;
    const float4* xv = (const float4*)x;
#pragma unroll
    for (int r = 0; r < 4; r++) {
        int idx = r * 128 + o;
        int i = idx >> 5, k4 = idx & 31;
        int node = n0 + i;
        xs[i][k4] = (node < n) ? xv[node * 32 + k4] : make_float4(0.f, 0.f, 0.f, 0.f);
    }
    __syncthreads();
    const float4* Wv = (const float4*)W;
    float acc[16];
#pragma unroll
    for (int i = 0; i < 16; i++) acc[i] = 0.f;
#pragma unroll 4
    for (int k4 = 0; k4 < 32; k4++) {
        float4 w = __ldg(&Wv[o * 32 + k4]);
#pragma unroll
        for (int i = 0; i < 16; i++) {
            float4 xq = xs[i][k4];
            acc[i] = fmaf(w.x, xq.x, fmaf(w.y, xq.y, fmaf(w.z, xq.z, fmaf(w.w, xq.w, acc[i]))));
        }
    }
#pragma unroll
    for (int i = 0; i < 16; i++) {
        int node = n0 + i;
        if (node < n) g_h1[node * 128 + o] = acc[i];
    }
}

// --------- per-node attention scalars, layer 1 (thread per (n,h)) ---------
__global__ void k_att1(const float* __restrict__ att_src, const float* __restrict__ att_dst, int n) {
    int t = blockIdx.x * blockDim.x + threadIdx.x;
    if (t >= n * 8) return;
    int nd = t >> 3, h = t & 7;
    const float4* hv = (const float4*)g_h1 + nd * 32 + h * 4;
    const float4* as = (const float4*)att_src + h * 4;
    const float4* ad = (const float4*)att_dst + h * 4;
    float sa = 0.f, sb = 0.f;
#pragma unroll
    for (int j = 0; j < 4; j++) {
        float4 hq = hv[j], aq = as[j], dq = ad[j];
        sa += hq.x*aq.x + hq.y*aq.y + hq.z*aq.z + hq.w*aq.w;
        sb += hq.x*dq.x + hq.y*dq.y + hq.z*dq.z + hq.w*dq.w;
    }
    g_sA1[t] = sa;   // pairs with dst
    g_sB1[t] = sb;   // pairs with src
}

// ------ layer1 fused gather: softmax-weighted agg + bias + ELU ------------
// one warp per dst node; lane = (head h = lane>>2, 4 channels = float4)
__global__ void k_gather1(const float* __restrict__ b1, int n) {
    int w = (blockIdx.x * blockDim.x + threadIdx.x) >> 5;
    if (w >= n) return;
    int lane = threadIdx.x & 31;
    int h = lane >> 2;
    int i   = g_rp[w];
    int end = g_rp[w + 1];
    float sAd = g_sA1[w * 8 + h];
    float4 acc = make_float4(0.f, 0.f, 0.f, 0.f);
    float dsum = 0.f;
    const float4* h1v = (const float4*)g_h1;
    int s = g_csr[i];                        // deg >= 1 always (self loop)
    for (;;) {
        int ni = i + 1;
        int sn = (ni < end) ? g_csr[ni] : 0; // prefetch next src id
        float sBs = g_sB1[s * 8 + h];
        float4 hv = h1v[s * 32 + lane];
        float ex = __expf(lrelu(sAd + sBs));
        acc.x = fmaf(ex, hv.x, acc.x);
        acc.y = fmaf(ex, hv.y, acc.y);
        acc.z = fmaf(ex, hv.z, acc.z);
        acc.w = fmaf(ex, hv.w, acc.w);
        dsum += ex;
        if (ni >= end) break;
        s = sn; i = ni;
    }
    float inv = 1.f / dsum;
    float4 b = ((const float4*)b1)[lane];
    float4 v;
    v.x = acc.x * inv + b.x;
    v.y = acc.y * inv + b.y;
    v.z = acc.z * inv + b.z;
    v.w = acc.w * inv + b.w;
    v.x = v.x > 0.f ? v.x : (__expf(v.x) - 1.f);
    v.y = v.y > 0.f ? v.y : (__expf(v.y) - 1.f);
    v.z = v.z > 0.f ? v.z : (__expf(v.z) - 1.f);
    v.w = v.w > 0.f ? v.w : (__expf(v.w) - 1.f);
    ((float4*)g_h1e)[w * 32 + lane] = v;
}

// ------------------- GEMM2: h2 = h1e @ W2^T  (N,128)x(128,16) -------------
__global__ void k_gemm2(const float* __restrict__ W2, int n) {
    __shared__ float4 xs[8][32];
    int tid = threadIdx.x;                   // 128 threads
    int n0 = blockIdx.x * 8;
    const float4* hv = (const float4*)g_h1e;
#pragma unroll
    for (int r = 0; r < 2; r++) {
        int idx = r * 128 + tid;
        int i = idx >> 5, k4 = idx & 31;
        int node = n0 + i;
        xs[i][k4] = (node < n) ? hv[node * 32 + k4] : make_float4(0.f, 0.f, 0.f, 0.f);
    }
    __syncthreads();
    int o = tid & 15, i = tid >> 4;
    const float4* Wv = (const float4*)W2;
    float acc = 0.f;
#pragma unroll 4
    for (int k4 = 0; k4 < 32; k4++) {
        float4 w = __ldg(&Wv[o * 32 + k4]);
        float4 xq = xs[i][k4];
        acc = fmaf(w.x, xq.x, fmaf(w.y, xq.y, fmaf(w.z, xq.z, fmaf(w.w, xq.w, acc))));
    }
    int node = n0 + i;
    if (node < n) g_h2[node * 16 + o] = acc;
}

// ------------- per-node attention scalars, layer 2 ------------------------
__global__ void k_att2(const float* __restrict__ att_src, const float* __restrict__ att_dst, int n) {
    int t = blockIdx.x * blockDim.x + threadIdx.x;
    if (t >= n) return;
    const float4* hv = (const float4*)g_h2 + t * 4;
    const float4* as = (const float4*)att_src;
    const float4* ad = (const float4*)att_dst;
    float sa = 0.f, sb = 0.f;
#pragma unroll
    for (int j = 0; j < 4; j++) {
        float4 hq = hv[j], aq = as[j], dq = ad[j];
        sa += hq.x*aq.x + hq.y*aq.y + hq.z*aq.z + hq.w*aq.w;
        sb += hq.x*dq.x + hq.y*dq.y + hq.z*dq.z + hq.w*dq.w;
    }
    g_sA2[t] = sa;
    g_sB2[t] = sb;
}

// ---- layer2 fused gather: softmax agg + bias + log_softmax ---------------
// 16-lane group per dst node (2 dsts per warp); lane = channel
__global__ void k_gather2(const float* __restrict__ b2, float* __restrict__ out, int n) {
    int gid = blockIdx.x * blockDim.x + threadIdx.x;
    int g0 = gid >> 4;
    int g = (g0 < n) ? g0 : (n - 1);         // clamp; keep full warp alive for shfl
    int c = gid & 15;
    int i   = g_rp[g];
    int end = g_rp[g + 1];
    float sAd = g_sA2[g];
    float acc = 0.f, dsum = 0.f;
    int s = g_csr[i];
    for (;;) {
        int ni = i + 1;
        int sn = (ni < end) ? g_csr[ni] : 0;
        float ex = __expf(lrelu(sAd + g_sB2[s]));
        acc = fmaf(ex, g_h2[s * 16 + c], acc);
        dsum += ex;
        if (ni >= end) break;
        s = sn; i = ni;
    }
    float v = acc / dsum + b2[c];
    // log-softmax across the 16 lanes of this dst
    float m = v;
#pragma unroll
    for (int o = 8; o; o >>= 1) m = fmaxf(m, __shfl_xor_sync(0xffffffffu, m, o, 16));
    float se = __expf(v - m), ssum = se;
#pragma unroll
    for (int o = 8; o; o >>= 1) ssum += __shfl_xor_sync(0xffffffffu, ssum, o, 16);
    if (g0 < n) out[g0 * 16 + c] = v - m - logf(ssum);
}

// ---------------------------------------------------------------------------
extern "C" void kernel_launch(void* const* d_in, const int* in_sizes, int n_in,
                              void* d_out, int out_size) {
    const float* x   = (const float*)d_in[0];
    const int*   ei  = (const int*)  d_in[1];
    const float* W1  = (const float*)d_in[2];
    const float* as1 = (const float*)d_in[3];
    const float* ad1 = (const float*)d_in[4];
    const float* b1  = (const float*)d_in[5];
    const float* W2  = (const float*)d_in[6];
    const float* as2 = (const float*)d_in[7];
    const float* ad2 = (const float*)d_in[8];
    const float* b2  = (const float*)d_in[9];
    float* out = (float*)d_out;

    int n  = in_sizes[0] / 128;   // 50000 nodes
    int e  = in_sizes[1] / 2;     // 1.6M edges (before self loops)
    int ep = e + n;

    const int BS = 256;
    // CSR build (reused by both layers)
    k_deginit<<<(n + BS - 1) / BS, BS>>>(n);
    k_hist   <<<(e + BS - 1) / BS, BS>>>(ei, e);
    k_scan   <<<1, 1024>>>(n);
    k_scatter<<<(ep + BS - 1) / BS, BS>>>(ei, e, n);
    // layer 1
    k_gemm1  <<<(n + 15) / 16, 128>>>(x, W1, n);
    k_att1   <<<(n * 8 + BS - 1) / BS, BS>>>(as1, ad1, n);
    k_gather1<<<(n * 32 + BS - 1) / BS, BS>>>(b1, n);
    // layer 2
    k_gemm2  <<<(n + 7) / 8, 128>>>(W2, n);
    k_att2   <<<(n + BS - 1) / BS, BS>>>(as2, ad2, n);
    k_gather2<<<(n * 16 + BS - 1) / BS, BS>>>(b2, out, n);
}